// round 11
// baseline (speedup 1.0000x reference)
#include <cuda_runtime.h>
#include <math.h>

#define Bb 2
#define Ll 1000
#define Dd 288
#define Hh 8
#define DIMv 36
#define DFFv 576
#define KSv 250
#define NQv 250
#define EPSv 1e-5f
#define NROW (Bb*Ll)
#define ST 128   // score GEMM tile

typedef unsigned long long ull;

__device__ __align__(16) float g_Wqt[Dd*Dd];
__device__ __align__(16) float g_Wkt[Dd*Dd];
__device__ __align__(16) float g_Wvt[Dd*Dd];
__device__ __align__(16) float g_W1t[Dd*DFFv];
__device__ __align__(16) float g_W2t[DFFv*Dd];
__device__ __align__(16) float g_q[Bb*Hh*Ll*DIMv];
__device__ __align__(16) float g_k[Bb*Hh*Ll*DIMv];
__device__ __align__(16) float g_v[Bb*Hh*Ll*DIMv];
__device__ __align__(16) float g_scores[Bb*Hh*Ll*Ll];   // 64 MB
__device__ __align__(16) float g_measure[Bb*Hh*Ll];
__device__ int g_idxq[Bb*Hh*NQv];
__device__ int g_cnt[Bb*Hh];
__device__ int g_flag[Bb*Hh*Ll];
__device__ __align__(16) float g_vmean[Bb*Hh*DIMv];
__device__ __align__(16) float g_attn[Bb*Ll*Dd];
__device__ __align__(16) float g_h1[Bb*Ll*Dd];
__device__ __align__(16) float g_f1[Bb*Ll*DFFv];
__device__ __align__(16) float g_h2[Bb*Ll*Dd];

__device__ __forceinline__ float warp_sum(float v) {
    #pragma unroll
    for (int o = 16; o; o >>= 1) v += __shfl_xor_sync(0xffffffffu, v, o);
    return v;
}
__device__ __forceinline__ float warp_max(float v) {
    #pragma unroll
    for (int o = 16; o; o >>= 1) v = fmaxf(v, __shfl_xor_sync(0xffffffffu, v, o));
    return v;
}
__device__ __forceinline__ float gelu_exact(float a) {
    return 0.5f * a * (1.0f + erff(a * 0.70710678118654752f));
}
__device__ __forceinline__ ull pk2(float lo, float hi) {
    ull r; asm("mov.b64 %0, {%1,%2};" : "=l"(r) : "f"(lo), "f"(hi)); return r;
}
__device__ __forceinline__ float2 upk2(ull v) {
    float2 f; asm("mov.b64 {%0,%1}, %2;" : "=f"(f.x), "=f"(f.y) : "l"(v)); return f;
}
__device__ __forceinline__ ull fma2_(ull a, ull b, ull c) {
    ull d; asm("fma.rn.f32x2 %0, %1, %2, %3;" : "=l"(d) : "l"(a), "l"(b), "l"(c)); return d;
}

__global__ void k_reset() { if (threadIdx.x < Bb*Hh) g_cnt[threadIdx.x] = 0; }

__global__ void k_transpose_all(const float* __restrict__ Wq, const float* __restrict__ Wk,
                                const float* __restrict__ Wv, const float* __restrict__ W1,
                                const float* __restrict__ W2) {
    int i = blockIdx.x * blockDim.x + threadIdx.x;
    const int SQ = Dd*Dd, SF = Dd*DFFv;
    if (i < SQ)            { int r=i/Dd, c=i%Dd;               g_Wqt[c*Dd+r]=Wq[i]; }
    else if (i < 2*SQ)     { int t=i-SQ,   r=t/Dd, c=t%Dd;     g_Wkt[c*Dd+r]=Wk[t]; }
    else if (i < 3*SQ)     { int t=i-2*SQ, r=t/Dd, c=t%Dd;     g_Wvt[c*Dd+r]=Wv[t]; }
    else if (i < 3*SQ+SF)  { int t=i-3*SQ, r=t/Dd, c=t%Dd;     g_W1t[c*DFFv+r]=W1[t]; }
    else if (i < 3*SQ+2*SF){ int t=i-3*SQ-SF, r=t/DFFv, c=t%DFFv; g_W2t[c*Dd+r]=W2[t]; }
}

// QKV: 16 rows/block, f32x2 packed row-pairs. 288 threads.
__global__ void __launch_bounds__(Dd) k_qkv(const float* __restrict__ x,
                                            const float* __restrict__ bq,
                                            const float* __restrict__ bk,
                                            const float* __restrict__ bv) {
    __shared__ ull xs2[Dd * 8];
    int base = blockIdx.x * 16, j = threadIdx.x;
    const float* xr = x + base * Dd + j;
    #pragma unroll
    for (int rp = 0; rp < 8; rp++)
        xs2[j * 8 + rp] = pk2(xr[(2*rp)*Dd], xr[(2*rp+1)*Dd]);
    __syncthreads();
    ull aq[8], ak[8], av[8];
    float bqj = bq[j], bkj = bk[j], bvj = bv[j];
    #pragma unroll
    for (int rp = 0; rp < 8; rp++) { aq[rp]=pk2(bqj,bqj); ak[rp]=pk2(bkj,bkj); av[rp]=pk2(bvj,bvj); }
    #pragma unroll 2
    for (int i = 0; i < Dd; i++) {
        ull wq = pk2(g_Wqt[i*Dd+j], g_Wqt[i*Dd+j]);
        ull wk = pk2(g_Wkt[i*Dd+j], g_Wkt[i*Dd+j]);
        ull wv = pk2(g_Wvt[i*Dd+j], g_Wvt[i*Dd+j]);
        #pragma unroll
        for (int rp = 0; rp < 8; rp++) {
            ull xv = xs2[i*8+rp];
            aq[rp]=fma2_(xv,wq,aq[rp]); ak[rp]=fma2_(xv,wk,ak[rp]); av[rp]=fma2_(xv,wv,av[rp]);
        }
    }
    int h = j / DIMv, dd = j % DIMv;
    #pragma unroll
    for (int rp = 0; rp < 8; rp++) {
        float2 q2=upk2(aq[rp]), k2=upk2(ak[rp]), v2=upk2(av[rp]);
        int r0 = base + 2*rp, r1 = r0 + 1;
        int o0 = (((r0/Ll)*Hh + h)*Ll + (r0%Ll))*DIMv + dd;
        int o1 = (((r1/Ll)*Hh + h)*Ll + (r1%Ll))*DIMv + dd;
        g_q[o0]=q2.x; g_k[o0]=k2.x; g_v[o0]=v2.x;
        g_q[o1]=q2.y; g_k[o1]=k2.y; g_v[o1]=v2.y;
    }
}

// Dense S = Q*K^T per head. 128x128 tile, 256 threads, 8x8 micro-tile, f32x2.
// grid (kt=8, qt=8, bh=16).
__global__ void __launch_bounds__(256, 2) k_scores() {
    __shared__ float Qs[DIMv][ST + 4];
    __shared__ float Ks[DIMv][ST + 4];
    int bh = blockIdx.z;
    int q0 = blockIdx.y * ST, k0 = blockIdx.x * ST;
    int tid = threadIdx.x;
    int tx = tid & 15, ty = tid >> 4;

    const float4* Qg = (const float4*)(g_q + bh * Ll * DIMv);
    const float4* Kg = (const float4*)(g_k + bh * Ll * DIMv);
    const float4 z4 = make_float4(0.f, 0.f, 0.f, 0.f);
    for (int u = tid; u < ST * 9; u += 256) {
        int r = u / 9, c = u % 9;
        float4 fq = (q0 + r < Ll) ? Qg[(q0 + r) * 9 + c] : z4;
        Qs[4*c+0][r]=fq.x; Qs[4*c+1][r]=fq.y; Qs[4*c+2][r]=fq.z; Qs[4*c+3][r]=fq.w;
        float4 fk = (k0 + r < Ll) ? Kg[(k0 + r) * 9 + c] : z4;
        Ks[4*c+0][r]=fk.x; Ks[4*c+1][r]=fk.y; Ks[4*c+2][r]=fk.z; Ks[4*c+3][r]=fk.w;
    }
    __syncthreads();

    ull acc[8][4];
    #pragma unroll
    for (int i = 0; i < 8; i++)
        #pragma unroll
        for (int j = 0; j < 4; j++) acc[i][j] = 0ull;

    #pragma unroll 2
    for (int d = 0; d < DIMv; d++) {
        float4 qa = *(const float4*)&Qs[d][ty * 8];
        float4 qb = *(const float4*)&Qs[d][ty * 8 + 4];
        float4 ka = *(const float4*)&Ks[d][tx * 8];
        float4 kb = *(const float4*)&Ks[d][tx * 8 + 4];
        ull kp0 = pk2(ka.x, ka.y), kp1 = pk2(ka.z, ka.w);
        ull kp2 = pk2(kb.x, kb.y), kp3 = pk2(kb.z, kb.w);
        float qv[8] = {qa.x, qa.y, qa.z, qa.w, qb.x, qb.y, qb.z, qb.w};
        #pragma unroll
        for (int i = 0; i < 8; i++) {
            ull qq = pk2(qv[i], qv[i]);
            acc[i][0] = fma2_(qq, kp0, acc[i][0]);
            acc[i][1] = fma2_(qq, kp1, acc[i][1]);
            acc[i][2] = fma2_(qq, kp2, acc[i][2]);
            acc[i][3] = fma2_(qq, kp3, acc[i][3]);
        }
    }

    float* Sb = g_scores + (size_t)bh * Ll * Ll;
    #pragma unroll
    for (int i = 0; i < 8; i++) {
        int q = q0 + ty * 8 + i;
        if (q < Ll) {
            #pragma unroll
            for (int j = 0; j < 2; j++) {
                int k = k0 + tx * 8 + j * 4;
                if (k < Ll) {
                    float2 ab = upk2(acc[i][2*j]), cd = upk2(acc[i][2*j+1]);
                    *(float4*)(Sb + (size_t)q * Ll + k) = make_float4(ab.x, ab.y, cd.x, cd.y);
                }
            }
        }
    }
}

// Measure from precomputed scores: warp loads its row to smem, gathers 250.
__global__ void __launch_bounds__(512) k_measure(const int* __restrict__ index_key) {
    extern __shared__ __align__(16) float rows[];   // 16 warps x 1000
    int bh = blockIdx.x >> 3, chunk = blockIdx.x & 7;
    int w = threadIdx.x >> 5, lane = threadIdx.x & 31;
    float* slot = rows + w * Ll;
    int q0 = chunk * 125;
    for (int ql = q0 + w; ql < q0 + 125; ql += 16) {
        const float4* src = (const float4*)(g_scores + ((size_t)bh * Ll + ql) * Ll);
        for (int i = lane; i < Ll / 4; i += 32) ((float4*)slot)[i] = src[i];
        __syncwarp();
        float mx = -1e30f, sm = 0.0f;
        for (int s = lane; s < KSv; s += 32) {
            int idx = index_key[ql * KSv + s];
            float v = slot[idx];
            mx = fmaxf(mx, v); sm += v;
        }
        mx = warp_max(mx); sm = warp_sum(sm);
        if (lane == 0) g_measure[bh * Ll + ql] = mx - sm * (1.0f / (float)Ll);
        __syncwarp();
    }
}

__global__ void k_topk() {
    __shared__ float ms[Ll];
    int bh = blockIdx.x >> 3, chunk = blockIdx.x & 7;
    for (int i = threadIdx.x; i < Ll; i += 128) ms[i] = g_measure[bh * Ll + i];
    __syncthreads();
    int t = chunk * 125 + threadIdx.x;
    if (threadIdx.x < 125) {
        float v = ms[t];
        int cnt = 0;
        #pragma unroll 4
        for (int jj = 0; jj < Ll; jj++) {
            float u = ms[jj];
            cnt += (u > v) || (u == v && jj < t);
        }
        int keep = (cnt < NQv) ? 1 : 0;
        g_flag[bh * Ll + t] = keep;
        if (keep) { int slot = atomicAdd(&g_cnt[bh], 1); g_idxq[bh * NQv + slot] = t; }
    }
}

// Tiled attention: scores streamed from g_scores; softmax + PV. 32 q/block.
#define OFF_SC    0
#define OFF_TILE  32000
#define OFF_PVRED 37796
#define OFF_SINV  42404
#define OFF_QIDX  42436
#define ATTN_SMEM_BYTES (42468*4)

__global__ void __launch_bounds__(288, 1) k_attn() {
    extern __shared__ __align__(16) float sm[];
    float* sc = sm + OFF_SC;            // [32][1000]
    float* tile = sm + OFF_TILE;        // vt[125][36]
    float4* pvred = (float4*)(sm + OFF_PVRED);
    float* sinv = sm + OFF_SINV;
    int* qidx = (int*)(sm + OFF_QIDX);

    int bh = blockIdx.x >> 3, qbase = (blockIdx.x & 7) * 32;
    int qcount = min(32, NQv - qbase);
    int tid = threadIdx.x, w = tid >> 5, lane = tid & 31;

    if (tid < 32) qidx[tid] = g_idxq[bh * NQv + qbase + min(tid, qcount - 1)];
    __syncthreads();

    // stream precomputed scores (scaled 1/sqrt(36))
    for (int u = tid; u < 32 * (Ll / 4); u += 288) {
        int q = u / (Ll / 4), i4 = u % (Ll / 4);
        float4 f = ((const float4*)(g_scores + ((size_t)bh * Ll + qidx[q]) * Ll))[i4];
        f.x *= (1.0f/6.0f); f.y *= (1.0f/6.0f); f.z *= (1.0f/6.0f); f.w *= (1.0f/6.0f);
        ((float4*)(sc + q * Ll))[i4] = f;
    }
    __syncthreads();

    // softmax: 9 warps, queries strided
    for (int q = w; q < 32; q += 9) {
        float* row = sc + q * Ll;
        float mx = -1e30f;
        for (int i = lane; i < Ll; i += 32) mx = fmaxf(mx, row[i]);
        mx = warp_max(mx);
        float sum = 0.0f;
        for (int i = lane; i < Ll; i += 32) { float e = __expf(row[i] - mx); row[i] = e; sum += e; }
        sum = warp_sum(sum);
        if (lane == 0) sinv[q] = 1.0f / sum;
    }
    __syncthreads();

    // PV: thread = (qg 0..7, dg 0..8, kp 0..3)
    int kp = tid & 3, sl = tid >> 2, qg = sl / 9, dg = sl % 9;
    ull acc[4][2];
    #pragma unroll
    for (int jq = 0; jq < 4; jq++) { acc[jq][0] = 0ull; acc[jq][1] = 0ull; }
    const float4* gv4 = (const float4*)(g_v + bh * Ll * DIMv);
    float4* vt4 = (float4*)tile;
    for (int t = 0; t < 8; t++) {
        int k0 = t * 125;
        __syncthreads();
        for (int u = tid; u < 125 * 9; u += 288) vt4[u] = gv4[k0 * 9 + u];
        __syncthreads();
        for (int kk = kp; kk < 125; kk += 4) {
            float4 v4 = vt4[kk * 9 + dg];
            ull vlo = pk2(v4.x, v4.y), vhi = pk2(v4.z, v4.w);
            #pragma unroll
            for (int jq = 0; jq < 4; jq++) {
                float pr = sc[(qg * 4 + jq) * Ll + k0 + kk];
                ull pp = pk2(pr, pr);
                acc[jq][0] = fma2_(pp, vlo, acc[jq][0]);
                acc[jq][1] = fma2_(pp, vhi, acc[jq][1]);
            }
        }
    }
    #pragma unroll
    for (int jq = 0; jq < 4; jq++) {
        float2 lo = upk2(acc[jq][0]), hi = upk2(acc[jq][1]);
        pvred[(sl * 4 + jq) * 4 + kp] = make_float4(lo.x, lo.y, hi.x, hi.y);
    }
    __syncthreads();
    {
        int u = tid, sl_u = u >> 2, jq_u = u & 3;
        int qg_u = sl_u / 9, dg_u = sl_u % 9, q = qg_u * 4 + jq_u;
        float4 a = pvred[u*4+0], b4 = pvred[u*4+1], c4 = pvred[u*4+2], d4 = pvred[u*4+3];
        float s = sinv[q];
        float4 o = make_float4((a.x+b4.x+c4.x+d4.x)*s, (a.y+b4.y+c4.y+d4.y)*s,
                               (a.z+b4.z+c4.z+d4.z)*s, (a.w+b4.w+c4.w+d4.w)*s);
        int b = bh >> 3, h = bh & 7;
        *(float4*)(g_attn + ((b*Ll + qidx[q])*Dd) + h*DIMv + dg_u*4) = o;
    }
}

__global__ void k_vmean() {
    __shared__ float red[288];
    int bh = blockIdx.x, tid = threadIdx.x;
    int sub = tid / DIMv, dd = tid % DIMv;
    float s = 0.0f;
    for (int l = sub; l < Ll; l += 8) s += g_v[(bh * Ll + l) * DIMv + dd];
    red[tid] = s;
    __syncthreads();
    if (sub == 0) {
        float tot = 0.0f;
        #pragma unroll
        for (int r = 0; r < 8; r++) tot += red[r * DIMv + dd];
        g_vmean[bh * DIMv + dd] = tot * (1.0f / (float)Ll);
    }
}

__global__ void k_fill() {
    int row = blockIdx.x, j = threadIdx.x;
    int b = row / Ll, l = row % Ll;
    int h = j / DIMv, dd = j % DIMv;
    int bh = b * Hh + h;
    if (!g_flag[bh * Ll + l]) g_attn[row * Dd + j] = g_vmean[bh * DIMv + dd];
}

__device__ __forceinline__ void ln_body(float v, int j, const float* gamma,
                                        const float* beta, float* out, int row,
                                        float* red9, float* bval) {
    int warp = j >> 5, lane = j & 31;
    float s = warp_sum(v);
    if (lane == 0) red9[warp] = s;
    __syncthreads();
    if (j == 0) { float t=0; for (int w=0;w<9;w++) t+=red9[w]; *bval=t; }
    __syncthreads();
    float mu = *bval * (1.0f / (float)Dd);
    float c = v - mu;
    __syncthreads();
    float s2 = warp_sum(c * c);
    if (lane == 0) red9[warp] = s2;
    __syncthreads();
    if (j == 0) { float t=0; for (int w=0;w<9;w++) t+=red9[w]; *bval=t; }
    __syncthreads();
    float var = *bval * (1.0f / (float)Dd);
    out[row * Dd + j] = c * rsqrtf(var + EPSv) * gamma[j] + beta[j];
}

__global__ void __launch_bounds__(Dd) k_res_ln(const float* __restrict__ a,
                                               const float* __restrict__ bsrc,
                                               const float* __restrict__ gamma,
                                               const float* __restrict__ beta,
                                               float* __restrict__ out) {
    __shared__ float red9[9]; __shared__ float bval;
    int row = blockIdx.x, j = threadIdx.x;
    ln_body(a[row*Dd+j] + bsrc[row*Dd+j], j, gamma, beta, out, row, red9, &bval);
}

__global__ void __launch_bounds__(Dd) k_ln(const float* __restrict__ a,
                                           const float* __restrict__ gamma,
                                           const float* __restrict__ beta,
                                           float* __restrict__ out) {
    __shared__ float red9[9]; __shared__ float bval;
    int row = blockIdx.x, j = threadIdx.x;
    ln_body(a[row*Dd+j], j, gamma, beta, out, row, red9, &bval);
}

// FFN1: 16 rows/block, 576 threads, f32x2.
__global__ void __launch_bounds__(DFFv) k_ffn1(const float* __restrict__ b1) {
    __shared__ ull xs2[Dd * 8];
    int base = blockIdx.x * 16, j = threadIdx.x;
    {
        int ii = j % Dd, half = j / Dd;
        const float* hr = g_h1 + base * Dd + ii;
        #pragma unroll
        for (int r = 0; r < 4; r++) {
            int rp = half * 4 + r;
            xs2[ii * 8 + rp] = pk2(hr[(2*rp)*Dd], hr[(2*rp+1)*Dd]);
        }
    }
    __syncthreads();
    ull acc[8];
    float bj = b1[j];
    #pragma unroll
    for (int rp = 0; rp < 8; rp++) acc[rp] = pk2(bj, bj);
    #pragma unroll 2
    for (int i = 0; i < Dd; i++) {
        ull w2 = pk2(g_W1t[i*DFFv+j], g_W1t[i*DFFv+j]);
        #pragma unroll
        for (int rp = 0; rp < 8; rp++) acc[rp] = fma2_(xs2[i*8+rp], w2, acc[rp]);
    }
    #pragma unroll
    for (int rp = 0; rp < 8; rp++) {
        float2 a2 = upk2(acc[rp]);
        g_f1[(base+2*rp)*DFFv + j]   = gelu_exact(a2.x);
        g_f1[(base+2*rp+1)*DFFv + j] = gelu_exact(a2.y);
    }
}

// FFN2 + residual: 16 rows/block, 288 threads, f32x2.
__global__ void __launch_bounds__(Dd) k_ffn2(const float* __restrict__ b2) {
    __shared__ ull fs2[DFFv * 8];
    int base = blockIdx.x * 16, j = threadIdx.x;
    #pragma unroll
    for (int cc = 0; cc < 2; cc++) {
        int ii = j + cc * Dd;
        const float* fr = g_f1 + base * DFFv + ii;
        #pragma unroll
        for (int rp = 0; rp < 8; rp++)
            fs2[ii * 8 + rp] = pk2(fr[(2*rp)*DFFv], fr[(2*rp+1)*DFFv]);
    }
    __syncthreads();
    ull acc[8];
    float bj = b2[j];
    #pragma unroll
    for (int rp = 0; rp < 8; rp++) acc[rp] = pk2(bj, bj);
    #pragma unroll 2
    for (int i = 0; i < DFFv; i++) {
        ull w2 = pk2(g_W2t[i*Dd+j], g_W2t[i*Dd+j]);
        #pragma unroll
        for (int rp = 0; rp < 8; rp++) acc[rp] = fma2_(fs2[i*8+rp], w2, acc[rp]);
    }
    #pragma unroll
    for (int rp = 0; rp < 8; rp++) {
        float2 a2 = upk2(acc[rp]);
        int r0 = base + 2*rp, r1 = r0 + 1;
        g_h2[r0*Dd+j] = gelu_exact(a2.x) + g_h1[r0*Dd+j];
        g_h2[r1*Dd+j] = gelu_exact(a2.y) + g_h1[r1*Dd+j];
    }
}

extern "C" void kernel_launch(void* const* d_in, const int* in_sizes, int n_in,
                              void* d_out, int out_size) {
    const float* x    = (const float*)d_in[0];
    const int*   ikey = (const int*)  d_in[1];
    const float* Wq   = (const float*)d_in[2];
    const float* bq   = (const float*)d_in[3];
    const float* Wk   = (const float*)d_in[4];
    const float* bk   = (const float*)d_in[5];
    const float* Wv   = (const float*)d_in[6];
    const float* bv   = (const float*)d_in[7];
    const float* W1   = (const float*)d_in[8];
    const float* b1   = (const float*)d_in[9];
    const float* W2   = (const float*)d_in[10];
    const float* b2   = (const float*)d_in[11];
    const float* ln1g = (const float*)d_in[12];
    const float* ln1b = (const float*)d_in[13];
    const float* ln2g = (const float*)d_in[14];
    const float* ln2b = (const float*)d_in[15];
    float* out = (float*)d_out;

    float *h1p, *h2p, *attnp;
    cudaGetSymbolAddress((void**)&h1p, g_h1);
    cudaGetSymbolAddress((void**)&h2p, g_h2);
    cudaGetSymbolAddress((void**)&attnp, g_attn);

    static const int MEAS_SMEM = 16 * Ll * sizeof(float);   // 64 KB
    cudaFuncSetAttribute(k_measure, cudaFuncAttributeMaxDynamicSharedMemorySize, MEAS_SMEM);
    cudaFuncSetAttribute(k_attn, cudaFuncAttributeMaxDynamicSharedMemorySize, ATTN_SMEM_BYTES);

    const int TTOT = 3*Dd*Dd + 2*Dd*DFFv;
    k_reset<<<1, 32>>>();
    k_transpose_all<<<(TTOT + 255)/256, 256>>>(Wq, Wk, Wv, W1, W2);
    k_qkv<<<NROW/16, Dd>>>(x, bq, bk, bv);
    k_scores<<<dim3(8, 8, Bb*Hh), 256>>>();
    k_measure<<<Bb*Hh*8, 512, MEAS_SMEM>>>(ikey);
    k_topk<<<Bb*Hh*8, 128>>>();
    k_attn<<<Bb*Hh*8, 288, ATTN_SMEM_BYTES>>>();
    k_vmean<<<Bb*Hh, 288>>>();
    k_fill<<<NROW, Dd>>>();
    k_res_ln<<<NROW, Dd>>>(x, attnp, ln1g, ln1b, h1p);
    k_ffn1<<<NROW/16, DFFv>>>(b1);
    k_ffn2<<<NROW/16, Dd>>>(b2);
    k_ln<<<NROW, Dd>>>(h2p, ln2g, ln2b, out);
}

// round 12
// speedup vs baseline: 1.0591x; 1.0591x over previous
#include <cuda_runtime.h>
#include <math.h>

#define Bb 2
#define Ll 1000
#define Dd 288
#define Hh 8
#define DIMv 36
#define DFFv 576
#define KSv 250
#define NQv 250
#define EPSv 1e-5f
#define NROW (Bb*Ll)

typedef unsigned long long ull;

__device__ __align__(16) float g_Wqt[Dd*Dd];
__device__ __align__(16) float g_Wkt[Dd*Dd];
__device__ __align__(16) float g_Wvt[Dd*Dd];
__device__ __align__(16) float g_W1t[Dd*DFFv];
__device__ __align__(16) float g_W2t[DFFv*Dd];
__device__ __align__(16) float g_q[Bb*Hh*Ll*DIMv];
__device__ __align__(16) float g_k[Bb*Hh*Ll*DIMv];
__device__ __align__(16) float g_v[Bb*Hh*Ll*DIMv];
__device__ __align__(16) float g_measure[Bb*Hh*Ll];
__device__ int g_idxq[Bb*Hh*NQv];
__device__ int g_cnt[Bb*Hh];
__device__ int g_flag[Bb*Hh*Ll];
__device__ __align__(16) float g_vmean[Bb*Hh*DIMv];
__device__ __align__(16) float g_attn[Bb*Ll*Dd];
__device__ __align__(16) float g_h1[Bb*Ll*Dd];
__device__ __align__(16) float g_f1[Bb*Ll*DFFv];

__device__ __forceinline__ float warp_sum(float v) {
    #pragma unroll
    for (int o = 16; o; o >>= 1) v += __shfl_xor_sync(0xffffffffu, v, o);
    return v;
}
__device__ __forceinline__ float warp_max(float v) {
    #pragma unroll
    for (int o = 16; o; o >>= 1) v = fmaxf(v, __shfl_xor_sync(0xffffffffu, v, o));
    return v;
}
__device__ __forceinline__ float gelu_exact(float a) {
    return 0.5f * a * (1.0f + erff(a * 0.70710678118654752f));
}
__device__ __forceinline__ ull pk2(float lo, float hi) {
    ull r; asm("mov.b64 %0, {%1,%2};" : "=l"(r) : "f"(lo), "f"(hi)); return r;
}
__device__ __forceinline__ float2 upk2(ull v) {
    float2 f; asm("mov.b64 {%0,%1}, %2;" : "=f"(f.x), "=f"(f.y) : "l"(v)); return f;
}
__device__ __forceinline__ ull fma2_(ull a, ull b, ull c) {
    ull d; asm("fma.rn.f32x2 %0, %1, %2, %3;" : "=l"(d) : "l"(a), "l"(b), "l"(c)); return d;
}

// transposes + g_cnt reset fused
__global__ void k_transpose_all(const float* __restrict__ Wq, const float* __restrict__ Wk,
                                const float* __restrict__ Wv, const float* __restrict__ W1,
                                const float* __restrict__ W2) {
    if (blockIdx.x == 0 && threadIdx.x < Bb*Hh) g_cnt[threadIdx.x] = 0;
    int i = blockIdx.x * blockDim.x + threadIdx.x;
    const int SQ = Dd*Dd, SF = Dd*DFFv;
    if (i < SQ)            { int r=i/Dd, c=i%Dd;               g_Wqt[c*Dd+r]=Wq[i]; }
    else if (i < 2*SQ)     { int t=i-SQ,   r=t/Dd, c=t%Dd;     g_Wkt[c*Dd+r]=Wk[t]; }
    else if (i < 3*SQ)     { int t=i-2*SQ, r=t/Dd, c=t%Dd;     g_Wvt[c*Dd+r]=Wv[t]; }
    else if (i < 3*SQ+SF)  { int t=i-3*SQ, r=t/Dd, c=t%Dd;     g_W1t[c*DFFv+r]=W1[t]; }
    else if (i < 3*SQ+2*SF){ int t=i-3*SQ-SF, r=t/DFFv, c=t%DFFv; g_W2t[c*Dd+r]=W2[t]; }
}

// QKV: 16 rows/block, f32x2 packed row-pairs. 288 threads.
__global__ void __launch_bounds__(Dd) k_qkv(const float* __restrict__ x,
                                            const float* __restrict__ bq,
                                            const float* __restrict__ bk,
                                            const float* __restrict__ bv) {
    __shared__ ull xs2[Dd * 8];
    int base = blockIdx.x * 16, j = threadIdx.x;
    const float* xr = x + base * Dd + j;
    #pragma unroll
    for (int rp = 0; rp < 8; rp++)
        xs2[j * 8 + rp] = pk2(xr[(2*rp)*Dd], xr[(2*rp+1)*Dd]);
    __syncthreads();
    ull aq[8], ak[8], av[8];
    float bqj = bq[j], bkj = bk[j], bvj = bv[j];
    #pragma unroll
    for (int rp = 0; rp < 8; rp++) { aq[rp]=pk2(bqj,bqj); ak[rp]=pk2(bkj,bkj); av[rp]=pk2(bvj,bvj); }
    #pragma unroll 2
    for (int i = 0; i < Dd; i++) {
        ull wq = pk2(g_Wqt[i*Dd+j], g_Wqt[i*Dd+j]);
        ull wk = pk2(g_Wkt[i*Dd+j], g_Wkt[i*Dd+j]);
        ull wv = pk2(g_Wvt[i*Dd+j], g_Wvt[i*Dd+j]);
        #pragma unroll
        for (int rp = 0; rp < 8; rp++) {
            ull xv = xs2[i*8+rp];
            aq[rp]=fma2_(xv,wq,aq[rp]); ak[rp]=fma2_(xv,wk,ak[rp]); av[rp]=fma2_(xv,wv,av[rp]);
        }
    }
    int h = j / DIMv, dd = j % DIMv;
    #pragma unroll
    for (int rp = 0; rp < 8; rp++) {
        float2 q2=upk2(aq[rp]), k2=upk2(ak[rp]), v2=upk2(av[rp]);
        int r0 = base + 2*rp, r1 = r0 + 1;
        int o0 = (((r0/Ll)*Hh + h)*Ll + (r0%Ll))*DIMv + dd;
        int o1 = (((r1/Ll)*Hh + h)*Ll + (r1%Ll))*DIMv + dd;
        g_q[o0]=q2.x; g_k[o0]=k2.x; g_v[o0]=v2.x;
        g_q[o1]=q2.y; g_k[o1]=k2.y; g_v[o1]=v2.y;
    }
}

__global__ void k_vmean() {
    __shared__ float red[288];
    int bh = blockIdx.x, tid = threadIdx.x;
    int sub = tid / DIMv, dd = tid % DIMv;
    float s = 0.0f;
    for (int l = sub; l < Ll; l += 8) s += g_v[(bh * Ll + l) * DIMv + dd];
    red[tid] = s;
    __syncthreads();
    if (sub == 0) {
        float tot = 0.0f;
        #pragma unroll
        for (int r = 0; r < 8; r++) tot += red[r * DIMv + dd];
        g_vmean[bh * DIMv + dd] = tot * (1.0f / (float)Ll);
    }
}

// Sampled measure: K tile in smem; 4 independent FMA chains per dot product.
__global__ void __launch_bounds__(512) k_measure(const int* __restrict__ index_key) {
    extern __shared__ __align__(16) float ks[];   // [1000][36]
    int bh = blockIdx.x >> 3, chunk = blockIdx.x & 7;
    const float4* kb4 = (const float4*)(g_k + bh * Ll * DIMv);
    for (int i = threadIdx.x; i < Ll * DIMv / 4; i += 512) ((float4*)ks)[i] = kb4[i];
    __syncthreads();
    int warp = threadIdx.x >> 5, lane = threadIdx.x & 31;
    const float* qb = g_q + bh * Ll * DIMv;
    int q0 = chunk * 125;
    for (int ql = q0 + warp; ql < q0 + 125; ql += 16) {
        float qreg[DIMv];
        #pragma unroll
        for (int d = 0; d < DIMv; d++) qreg[d] = qb[ql * DIMv + d];
        const int* ik = index_key + ql * KSv;
        float mx = -1e30f, sm = 0.0f;
        #pragma unroll 2
        for (int s = lane; s < KSv; s += 32) {
            int idx = ik[s];
            const float4* kr = (const float4*)(ks + idx * DIMv);
            float a0 = 0.f, a1 = 0.f, a2 = 0.f, a3 = 0.f;
            #pragma unroll
            for (int p = 0; p < 9; p++) {
                float4 kv = kr[p];
                a0 = fmaf(qreg[4*p+0], kv.x, a0);
                a1 = fmaf(qreg[4*p+1], kv.y, a1);
                a2 = fmaf(qreg[4*p+2], kv.z, a2);
                a3 = fmaf(qreg[4*p+3], kv.w, a3);
            }
            float acc = (a0 + a1) + (a2 + a3);
            mx = fmaxf(mx, acc); sm += acc;
        }
        mx = warp_max(mx); sm = warp_sum(sm);
        if (lane == 0) g_measure[bh * Ll + ql] = mx - sm * (1.0f / (float)Ll);
    }
}

__global__ void k_topk() {
    __shared__ float ms[Ll];
    int bh = blockIdx.x >> 3, chunk = blockIdx.x & 7;
    for (int i = threadIdx.x; i < Ll; i += 128) ms[i] = g_measure[bh * Ll + i];
    __syncthreads();
    int t = chunk * 125 + threadIdx.x;
    if (threadIdx.x < 125) {
        float v = ms[t];
        int cnt = 0;
        #pragma unroll 4
        for (int jj = 0; jj < Ll; jj++) {
            float u = ms[jj];
            cnt += (u > v) || (u == v && jj < t);
        }
        int keep = (cnt < NQv) ? 1 : 0;
        g_flag[bh * Ll + t] = keep;
        if (keep) { int slot = atomicAdd(&g_cnt[bh], 1); g_idxq[bh * NQv + slot] = t; }
    }
}

// Tiled attention: 32 queries/block, grid 16*8, 288 threads. (R8 version)
#define OFF_SC    0
#define OFF_TILE  32000
#define OFF_QS    36644
#define OFF_PVRED 37796
#define OFF_SINV  42404
#define OFF_QIDX  42436
#define ATTN_SMEM_BYTES (42468*4)

__global__ void __launch_bounds__(288, 1) k_attn() {
    extern __shared__ __align__(16) float sm[];
    float* sc = sm + OFF_SC;
    float* tile = sm + OFF_TILE;
    float* qs = sm + OFF_QS;
    float4* pvred = (float4*)(sm + OFF_PVRED);
    float* sinv = sm + OFF_SINV;
    int* qidx = (int*)(sm + OFF_QIDX);

    int bh = blockIdx.x >> 3, qbase = (blockIdx.x & 7) * 32;
    int qcount = min(32, NQv - qbase);
    int tid = threadIdx.x, w = tid >> 5, lane = tid & 31;

    if (tid < 32) qidx[tid] = g_idxq[bh * NQv + qbase + min(tid, qcount - 1)];
    __syncthreads();
    for (int u = tid; u < 32 * DIMv; u += 288) {
        int q = u / DIMv, d = u % DIMv;
        qs[u] = g_q[(bh * Ll + qidx[q]) * DIMv + d] * (1.0f / 6.0f);
    }
    __syncthreads();

    const float4* gk4 = (const float4*)(g_k + bh * Ll * DIMv);
    for (int p = 0; p < 2; p++) {
        ull qp[DIMv];
        int q0 = 2 * (p * 8 + w);
        if (w < 8) {
            #pragma unroll
            for (int d = 0; d < DIMv; d++) qp[d] = pk2(qs[q0*DIMv+d], qs[(q0+1)*DIMv+d]);
        }
        for (int t = 0; t < 8; t++) {
            int k0 = t * 125;
            __syncthreads();
            for (int u = tid; u < 125 * 9; u += 288) {
                int kk = u / 9, c = u % 9;
                float4 f = gk4[(k0 + kk) * 9 + c];
                tile[(4*c+0)*129+kk]=f.x; tile[(4*c+1)*129+kk]=f.y;
                tile[(4*c+2)*129+kk]=f.z; tile[(4*c+3)*129+kk]=f.w;
            }
            __syncthreads();
            if (w < 8) {
                #pragma unroll
                for (int i = 0; i < 4; i++) {
                    int kk = lane + 32 * i;
                    if (kk < 125) {
                        ull a = 0ull;
                        #pragma unroll
                        for (int d = 0; d < DIMv; d++) {
                            float kd = tile[d * 129 + kk];
                            a = fma2_(qp[d], pk2(kd, kd), a);
                        }
                        float2 r = upk2(a);
                        sc[q0 * Ll + k0 + kk] = r.x;
                        sc[(q0+1) * Ll + k0 + kk] = r.y;
                    }
                }
            }
        }
    }
    __syncthreads();

    for (int q = w; q < 32; q += 9) {
        float* row = sc + q * Ll;
        float mx = -1e30f;
        for (int i = lane; i < Ll; i += 32) mx = fmaxf(mx, row[i]);
        mx = warp_max(mx);
        float sum = 0.0f;
        for (int i = lane; i < Ll; i += 32) { float e = __expf(row[i] - mx); row[i] = e; sum += e; }
        sum = warp_sum(sum);
        if (lane == 0) sinv[q] = 1.0f / sum;
    }
    __syncthreads();

    int kp = tid & 3, sl = tid >> 2, qg = sl / 9, dg = sl % 9;
    ull acc[4][2];
    #pragma unroll
    for (int jq = 0; jq < 4; jq++) { acc[jq][0] = 0ull; acc[jq][1] = 0ull; }
    const float4* gv4 = (const float4*)(g_v + bh * Ll * DIMv);
    float4* vt4 = (float4*)tile;
    for (int t = 0; t < 8; t++) {
        int k0 = t * 125;
        __syncthreads();
        for (int u = tid; u < 125 * 9; u += 288) vt4[u] = gv4[k0 * 9 + u];
        __syncthreads();
        for (int kk = kp; kk < 125; kk += 4) {
            float4 v4 = vt4[kk * 9 + dg];
            ull vlo = pk2(v4.x, v4.y), vhi = pk2(v4.z, v4.w);
            #pragma unroll
            for (int jq = 0; jq < 4; jq++) {
                float pr = sc[(qg * 4 + jq) * Ll + k0 + kk];
                ull pp = pk2(pr, pr);
                acc[jq][0] = fma2_(pp, vlo, acc[jq][0]);
                acc[jq][1] = fma2_(pp, vhi, acc[jq][1]);
            }
        }
    }
    #pragma unroll
    for (int jq = 0; jq < 4; jq++) {
        float2 lo = upk2(acc[jq][0]), hi = upk2(acc[jq][1]);
        pvred[(sl * 4 + jq) * 4 + kp] = make_float4(lo.x, lo.y, hi.x, hi.y);
    }
    __syncthreads();
    {
        int u = tid, sl_u = u >> 2, jq_u = u & 3;
        int qg_u = sl_u / 9, dg_u = sl_u % 9, q = qg_u * 4 + jq_u;
        float4 a = pvred[u*4+0], b4 = pvred[u*4+1], c4 = pvred[u*4+2], d4 = pvred[u*4+3];
        float s = sinv[q];
        float4 o = make_float4((a.x+b4.x+c4.x+d4.x)*s, (a.y+b4.y+c4.y+d4.y)*s,
                               (a.z+b4.z+c4.z+d4.z)*s, (a.w+b4.w+c4.w+d4.w)*s);
        int b = bh >> 3, h = bh & 7;
        *(float4*)(g_attn + ((b*Ll + qidx[q])*Dd) + h*DIMv + dg_u*4) = o;
    }
}

// h1 = LN1(x + (flag ? attn : vmean)) — fill fused in.
__global__ void __launch_bounds__(Dd) k_res_ln(const float* __restrict__ x,
                                               const float* __restrict__ gamma,
                                               const float* __restrict__ beta) {
    __shared__ float red9[9]; __shared__ float bval;
    int row = blockIdx.x, j = threadIdx.x;
    int b = row / Ll, l = row % Ll;
    int h = j / DIMv, dd = j % DIMv;
    int bh = b * Hh + h;
    float av = g_flag[bh * Ll + l] ? g_attn[row * Dd + j] : g_vmean[bh * DIMv + dd];
    float v = x[row * Dd + j] + av;
    int warp = j >> 5, lane = j & 31;
    float s = warp_sum(v);
    if (lane == 0) red9[warp] = s;
    __syncthreads();
    if (j == 0) { float t=0; for (int w=0;w<9;w++) t+=red9[w]; bval=t; }
    __syncthreads();
    float mu = bval * (1.0f / (float)Dd);
    float c = v - mu;
    __syncthreads();
    float s2 = warp_sum(c * c);
    if (lane == 0) red9[warp] = s2;
    __syncthreads();
    if (j == 0) { float t=0; for (int w=0;w<9;w++) t+=red9[w]; bval=t; }
    __syncthreads();
    float var = bval * (1.0f / (float)Dd);
    g_h1[row * Dd + j] = c * rsqrtf(var + EPSv) * gamma[j] + beta[j];
}

// FFN1: 16 rows/block, 576 threads, f32x2.
__global__ void __launch_bounds__(DFFv) k_ffn1(const float* __restrict__ b1) {
    __shared__ ull xs2[Dd * 8];
    int base = blockIdx.x * 16, j = threadIdx.x;
    {
        int ii = j % Dd, half = j / Dd;
        const float* hr = g_h1 + base * Dd + ii;
        #pragma unroll
        for (int r = 0; r < 4; r++) {
            int rp = half * 4 + r;
            xs2[ii * 8 + rp] = pk2(hr[(2*rp)*Dd], hr[(2*rp+1)*Dd]);
        }
    }
    __syncthreads();
    ull acc[8];
    float bj = b1[j];
    #pragma unroll
    for (int rp = 0; rp < 8; rp++) acc[rp] = pk2(bj, bj);
    #pragma unroll 2
    for (int i = 0; i < Dd; i++) {
        ull w2 = pk2(g_W1t[i*DFFv+j], g_W1t[i*DFFv+j]);
        #pragma unroll
        for (int rp = 0; rp < 8; rp++) acc[rp] = fma2_(xs2[i*8+rp], w2, acc[rp]);
    }
    #pragma unroll
    for (int rp = 0; rp < 8; rp++) {
        float2 a2 = upk2(acc[rp]);
        g_f1[(base+2*rp)*DFFv + j]   = gelu_exact(a2.x);
        g_f1[(base+2*rp+1)*DFFv + j] = gelu_exact(a2.y);
    }
}

// FFN2 + residual + LN2, writes final output. 16 rows/block, 288 threads.
__global__ void __launch_bounds__(Dd) k_ffn2_ln(const float* __restrict__ b2,
                                                const float* __restrict__ gamma,
                                                const float* __restrict__ beta,
                                                float* __restrict__ out) {
    __shared__ ull fs2[DFFv * 8];          // 36864 B; reused as h2s after GEMM
    __shared__ float mu_s[16], rs_s[16];
    int base = blockIdx.x * 16, j = threadIdx.x;
    int w = j >> 5, lane = j & 31;
    #pragma unroll
    for (int cc = 0; cc < 2; cc++) {
        int ii = j + cc * Dd;
        const float* fr = g_f1 + base * DFFv + ii;
        #pragma unroll
        for (int rp = 0; rp < 8; rp++)
            fs2[ii * 8 + rp] = pk2(fr[(2*rp)*DFFv], fr[(2*rp+1)*DFFv]);
    }
    __syncthreads();
    ull acc[8];
    float bj = b2[j];
    #pragma unroll
    for (int rp = 0; rp < 8; rp++) acc[rp] = pk2(bj, bj);
    #pragma unroll 2
    for (int i = 0; i < DFFv; i++) {
        ull w2 = pk2(g_W2t[i*Dd+j], g_W2t[i*Dd+j]);
        #pragma unroll
        for (int rp = 0; rp < 8; rp++) acc[rp] = fma2_(fs2[i*8+rp], w2, acc[rp]);
    }
    // h2 values in registers
    float hv[16];
    #pragma unroll
    for (int rp = 0; rp < 8; rp++) {
        float2 a2 = upk2(acc[rp]);
        int r0 = base + 2*rp;
        hv[2*rp]   = gelu_exact(a2.x) + g_h1[r0*Dd + j];
        hv[2*rp+1] = gelu_exact(a2.y) + g_h1[(r0+1)*Dd + j];
    }
    __syncthreads();                       // all fs2 reads done
    float* h2s = (float*)fs2;              // [16][296]
    #pragma unroll
    for (int r = 0; r < 16; r++) h2s[r * 296 + j] = hv[r];
    __syncthreads();
    // LN per row: 9 warps over 16 rows, two-pass
    for (int row = w; row < 16; row += 9) {
        float s = 0.0f;
        #pragma unroll
        for (int kk = 0; kk < 9; kk++) s += h2s[row * 296 + lane + 32 * kk];
        s = warp_sum(s);
        float mu = s * (1.0f / (float)Dd);
        float sq = 0.0f;
        #pragma unroll
        for (int kk = 0; kk < 9; kk++) {
            float c = h2s[row * 296 + lane + 32 * kk] - mu;
            sq += c * c;
        }
        sq = warp_sum(sq);
        if (lane == 0) {
            mu_s[row] = mu;
            rs_s[row] = rsqrtf(sq * (1.0f / (float)Dd) + EPSv);
        }
    }
    __syncthreads();
    float gj = gamma[j], bj2 = beta[j];
    #pragma unroll
    for (int r = 0; r < 16; r++)
        out[(base + r) * Dd + j] = (hv[r] - mu_s[r]) * rs_s[r] * gj + bj2;
}

extern "C" void kernel_launch(void* const* d_in, const int* in_sizes, int n_in,
                              void* d_out, int out_size) {
    const float* x    = (const float*)d_in[0];
    const int*   ikey = (const int*)  d_in[1];
    const float* Wq   = (const float*)d_in[2];
    const float* bq   = (const float*)d_in[3];
    const float* Wk   = (const float*)d_in[4];
    const float* bk   = (const float*)d_in[5];
    const float* Wv   = (const float*)d_in[6];
    const float* bv   = (const float*)d_in[7];
    const float* W1   = (const float*)d_in[8];
    const float* b1   = (const float*)d_in[9];
    const float* W2   = (const float*)d_in[10];
    const float* b2   = (const float*)d_in[11];
    const float* ln1g = (const float*)d_in[12];
    const float* ln1b = (const float*)d_in[13];
    const float* ln2g = (const float*)d_in[14];
    const float* ln2b = (const float*)d_in[15];
    float* out = (float*)d_out;

    static const int MEAS_SMEM = Ll * DIMv * sizeof(float);   // 144000
    cudaFuncSetAttribute(k_measure, cudaFuncAttributeMaxDynamicSharedMemorySize, MEAS_SMEM);
    cudaFuncSetAttribute(k_attn, cudaFuncAttributeMaxDynamicSharedMemorySize, ATTN_SMEM_BYTES);

    const int TTOT = 3*Dd*Dd + 2*Dd*DFFv;
    k_transpose_all<<<(TTOT + 255)/256, 256>>>(Wq, Wk, Wv, W1, W2);   // 0
    k_qkv<<<NROW/16, Dd>>>(x, bq, bk, bv);                            // 1
    k_vmean<<<Bb*Hh, 288>>>();                                        // 2
    k_measure<<<Bb*Hh*8, 512, MEAS_SMEM>>>(ikey);                     // 3 <- ncu slot
    k_topk<<<Bb*Hh*8, 128>>>();                                       // 4
    k_attn<<<Bb*Hh*8, 288, ATTN_SMEM_BYTES>>>();                      // 5
    k_res_ln<<<NROW, Dd>>>(x, ln1g, ln1b);                            // 6
    k_ffn1<<<NROW/16, DFFv>>>(b1);                                    // 7
    k_ffn2_ln<<<NROW/16, Dd>>>(b2, ln2g, ln2b, out);                  // 8
}